// round 15
// baseline (speedup 1.0000x reference)
#include <cuda_runtime.h>
#include <math.h>
#include <stdint.h>

#define NN   50000
#define EE   400000
#define DIN  128
#define HH   10
#define HID  320
#define DOUT 32
#define NEGS 0.2f
#define EPSBN 1e-5f

// ---------------- scratch ----------------
__device__ float g_xl1[(size_t)NN * HID];
__device__ float g_xr1[(size_t)NN * HID];
__device__ float g_h  [(size_t)NN * HID];
__device__ float g_xl2[NN * DOUT];
__device__ float g_xr2[NN * DOUT];
__device__ int   g_deg[NN];
__device__ int   g_off[NN + 1];
__device__ int   g_cur[NN];
__device__ int   g_esrc[EE];
__device__ float g_bnsum[HID];
__device__ float g_bnsumsq[HID];
__device__ float g_bnA[HID];
__device__ float g_bnB[HID];

__device__ __forceinline__ float wsum(float v) {
    #pragma unroll
    for (int o = 16; o; o >>= 1) v += __shfl_xor_sync(0xffffffffu, v, o);
    return v;
}
__device__ __forceinline__ float wmax(float v) {
    #pragma unroll
    for (int o = 16; o; o >>= 1) v = fmaxf(v, __shfl_xor_sync(0xffffffffu, v, o));
    return v;
}
__device__ __forceinline__ uint32_t f2tf(float f) {
    uint32_t u;
    asm("cvt.rna.tf32.f32 %0, %1;" : "=r"(u) : "f"(f));
    return u;
}
__device__ __forceinline__ void mma_tf32(float c[4], const uint32_t a[4], const uint32_t b[2]) {
    asm("mma.sync.aligned.m16n8k8.row.col.f32.tf32.tf32.f32 "
        "{%0,%1,%2,%3}, {%4,%5,%6,%7}, {%8,%9}, {%0,%1,%2,%3};"
        : "+f"(c[0]), "+f"(c[1]), "+f"(c[2]), "+f"(c[3])
        : "r"(a[0]), "r"(a[1]), "r"(a[2]), "r"(a[3]), "r"(b[0]), "r"(b[1]));
}

// ---------------- setup ----------------
__global__ void k_zero() {
    int i = blockIdx.x * blockDim.x + threadIdx.x;
    if (i < NN) g_deg[i] = 0;
    if (i < HID) { g_bnsum[i] = 0.f; g_bnsumsq[i] = 0.f; }
}
__global__ void k_deg(const int* __restrict__ dst) {
    int e = blockIdx.x * blockDim.x + threadIdx.x;
    if (e < EE) atomicAdd(&g_deg[dst[e]], 1);
}
__global__ void k_scan2() {
    __shared__ int wsums[32];
    const int t = threadIdx.x;
    const int C = (NN + 1023) / 1024;
    int i0 = t * C;
    int i1 = min(i0 + C, NN);
    if (i0 > NN) i0 = NN;
    int s = 0;
    for (int i = i0; i < i1; i++) s += g_deg[i];
    int lane = t & 31, wid = t >> 5;
    int v = s;
    #pragma unroll
    for (int o = 1; o < 32; o <<= 1) {
        int x = __shfl_up_sync(0xffffffffu, v, o);
        if (lane >= o) v += x;
    }
    if (lane == 31) wsums[wid] = v;
    __syncthreads();
    if (wid == 0) {
        int wv = wsums[lane];
        #pragma unroll
        for (int o = 1; o < 32; o <<= 1) {
            int x = __shfl_up_sync(0xffffffffu, wv, o);
            if (lane >= o) wv += x;
        }
        wsums[lane] = wv;
    }
    __syncthreads();
    int base = v - s + (wid ? wsums[wid - 1] : 0);
    int run = base;
    for (int i = i0; i < i1; i++) {
        g_off[i] = run; g_cur[i] = run;
        run += g_deg[i];
    }
    if (t == 0) g_off[NN] = wsums[31];
}
__global__ void k_scatter(const int* __restrict__ src, const int* __restrict__ dst) {
    int e = blockIdx.x * blockDim.x + threadIdx.x;
    if (e >= EE) return;
    int p = atomicAdd(&g_cur[dst[e]], 1);
    g_esrc[p] = src[e];
}

// ---------------- tf32 tensor-core GEMM, fragment-ordered smem ----------------
template<int BM, int BN, int WROWS, int WCOLS, bool FUSEBN>
__global__ __launch_bounds__(256, 2) void gemm_tc(
        const float* __restrict__ A,
        const float* __restrict__ W1, const float* __restrict__ B1,
        const float* __restrict__ W2, const float* __restrict__ B2,
        const float* __restrict__ pa,
        float* __restrict__ XL, float* __restrict__ XR,
        int M, int K, int NW) {
    constexpr int BK = 32;
    constexpr int WM = BM / WROWS;
    constexpr int WN = BN / WCOLS;
    constexpr int MT = WM / 16;
    constexpr int NT = WN / 8;
    constexpr int MBLK = BM / 16;
    constexpr int NBLK = BN / 8;
    __shared__ __align__(16) uint32_t As_f[BK / 8 * MBLK * 128];
    __shared__ __align__(16) uint32_t Bs_f[BK / 8 * NBLK * 64];
    const int tid = threadIdx.x;
    const int lane = tid & 31;
    const int w = tid >> 5;
    const int wr = w / WCOLS, wc = w % WCOLS;
    const int wm0 = wr * WM, wn0 = wc * WN;
    const int gID = lane >> 2, tIG = lane & 3;
    const int bm = blockIdx.x * BM;
    const int bn = blockIdx.y * BN;
    const float ap = FUSEBN ? pa[0] : 0.f;

    float c[MT][NT][4];
    #pragma unroll
    for (int i = 0; i < MT; i++)
        #pragma unroll
        for (int j = 0; j < NT; j++)
            { c[i][j][0] = 0.f; c[i][j][1] = 0.f; c[i][j][2] = 0.f; c[i][j][3] = 0.f; }

    for (int k0 = 0; k0 < K; k0 += BK) {
        // A tile (fragment-ordered store)
        #pragma unroll
        for (int fid = tid; fid < BM * BK / 4; fid += 256) {
            int r = fid >> 3;
            int kc4 = (fid & 7) * 4;
            float4 v = make_float4(0.f, 0.f, 0.f, 0.f);
            int gr = bm + r;
            if (gr < M) {
                v = *reinterpret_cast<const float4*>(A + (size_t)gr * K + k0 + kc4);
                if (FUSEBN) {
                    float4 sA = *reinterpret_cast<const float4*>(&g_bnA[k0 + kc4]);
                    float4 sB = *reinterpret_cast<const float4*>(&g_bnB[k0 + kc4]);
                    v.x = v.x * sA.x + sB.x; v.x = v.x >= 0.f ? v.x : ap * v.x;
                    v.y = v.y * sA.y + sB.y; v.y = v.y >= 0.f ? v.y : ap * v.y;
                    v.z = v.z * sA.z + sB.z; v.z = v.z >= 0.f ? v.z : ap * v.z;
                    v.w = v.w * sA.w + sB.w; v.w = v.w >= 0.f ? v.w : ap * v.w;
                }
            }
            int mb = r >> 4, m7 = r & 7, mbit = (r >> 3) & 1;
            float vv[4] = {v.x, v.y, v.z, v.w};
            #pragma unroll
            for (int i = 0; i < 4; i++) {
                int k = kc4 + i;
                int kb = k >> 3, k3 = k & 3, kreg = (k >> 2) & 1;
                int o = (m7 * 4 + k3) * 4 + mbit + 2 * kreg;
                As_f[(kb * MBLK + mb) * 128 + (o ^ (kb << 2))] = f2tf(vv[i]);
            }
        }
        // B tile (fragment-ordered store)
        #pragma unroll
        for (int fid = tid; fid < BK * BN / 4; fid += 256) {
            int kr = fid / (BN / 4);
            int nc4 = (fid % (BN / 4)) * 4;
            int gn = bn + nc4;
            const float* Wp; int col;
            if (gn < NW) { Wp = W1; col = gn; } else { Wp = W2; col = gn - NW; }
            float4 v = *reinterpret_cast<const float4*>(Wp + (size_t)(k0 + kr) * NW + col);
            int kb = kr >> 3, k3 = kr & 3, kreg = (kr >> 2) & 1;
            float vv[4] = {v.x, v.y, v.z, v.w};
            #pragma unroll
            for (int i = 0; i < 4; i++) {
                int nn2 = nc4 + i;
                int nb = nn2 >> 3, n7 = nn2 & 7;
                int o = (n7 * 4 + k3) * 2 + kreg;
                Bs_f[(kb * NBLK + nb) * 64 + (o ^ ((nb & 15) << 1))] = f2tf(vv[i]);
            }
        }
        __syncthreads();
        #pragma unroll
        for (int kk = 0; kk < BK / 8; kk++) {
            uint32_t afr[MT][4], bfr[NT][2];
            #pragma unroll
            for (int mt = 0; mt < MT; mt++) {
                int blk = kk * MBLK + (wm0 >> 4) + mt;
                uint4 u = *reinterpret_cast<const uint4*>(
                    &As_f[blk * 128 + ((lane ^ kk) << 2)]);
                afr[mt][0] = u.x; afr[mt][1] = u.y; afr[mt][2] = u.z; afr[mt][3] = u.w;
            }
            #pragma unroll
            for (int nt = 0; nt < NT; nt++) {
                int nb = (wn0 >> 3) + nt;
                int blk = kk * NBLK + nb;
                uint2 u = *reinterpret_cast<const uint2*>(
                    &Bs_f[blk * 64 + ((lane ^ (nb & 15)) << 1)]);
                bfr[nt][0] = u.x; bfr[nt][1] = u.y;
            }
            #pragma unroll
            for (int mt = 0; mt < MT; mt++)
                #pragma unroll
                for (int nt = 0; nt < NT; nt++)
                    mma_tf32(c[mt][nt], afr[mt], bfr[nt]);
        }
        __syncthreads();
    }

    #pragma unroll
    for (int mt = 0; mt < MT; mt++) {
        int r0 = bm + wm0 + mt * 16 + gID;
        int r1 = r0 + 8;
        #pragma unroll
        for (int nt = 0; nt < NT; nt++) {
            int col = bn + wn0 + nt * 8 + tIG * 2;
            float* Xp; const float* Bp; int cc;
            if (col < NW) { Xp = XL; Bp = B1; cc = col; }
            else          { Xp = XR; Bp = B2; cc = col - NW; }
            float b0 = Bp[cc], b1 = Bp[cc + 1];
            if (r0 < M) {
                float2 v = make_float2(c[mt][nt][0] + b0, c[mt][nt][1] + b1);
                *reinterpret_cast<float2*>(Xp + (size_t)r0 * NW + cc) = v;
            }
            if (r1 < M) {
                float2 v = make_float2(c[mt][nt][2] + b0, c[mt][nt][3] + b1);
                *reinterpret_cast<float2*>(Xp + (size_t)r1 * NW + cc) = v;
            }
        }
    }
}

// ---------------- fused layer-1 edge phase: predicated batch-4 (no serial remainder) ----------------
__global__ void k_l1fused(const float* __restrict__ att) {
    int gw = (blockIdx.x * blockDim.x + threadIdx.x) >> 5;
    int lane = threadIdx.x & 31;
    if (gw >= NN * HH) return;
    int n = gw / HH, h = gw - (gw / HH) * HH;
    int off = h * 32 + lane;
    float xr = g_xr1[(size_t)n * HID + off];
    float av = att[off];
    int p = g_off[n], end = g_off[n + 1];
    float den = 0.f, acc = 0.f;
    for (int base = p; base < end; base += 4) {
        int last = end - 1;
        int e1 = min(base + 1, last), e2 = min(base + 2, last), e3 = min(base + 3, last);
        int s0 = g_esrc[base], s1 = g_esrc[e1];
        int s2 = g_esrc[e2],   s3 = g_esrc[e3];
        float m1 = (base + 1 <= last) ? 1.f : 0.f;
        float m2 = (base + 2 <= last) ? 1.f : 0.f;
        float m3 = (base + 3 <= last) ? 1.f : 0.f;
        float x0 = g_xl1[(size_t)s0 * HID + off];
        float x1 = g_xl1[(size_t)s1 * HID + off];
        float x2 = g_xl1[(size_t)s2 * HID + off];
        float x3 = g_xl1[(size_t)s3 * HID + off];
        float t0 = x0 + xr; t0 = t0 >= 0.f ? t0 : NEGS * t0;
        float t1 = x1 + xr; t1 = t1 >= 0.f ? t1 : NEGS * t1;
        float t2 = x2 + xr; t2 = t2 >= 0.f ? t2 : NEGS * t2;
        float t3 = x3 + xr; t3 = t3 >= 0.f ? t3 : NEGS * t3;
        float f0 = __expf(wsum(t0 * av));
        float f1 = m1 * __expf(wsum(t1 * av));
        float f2 = m2 * __expf(wsum(t2 * av));
        float f3 = m3 * __expf(wsum(t3 * av));
        den += (f0 + f1) + (f2 + f3);
        acc += (f0 * x0 + f1 * x1) + (f2 * x2 + f3 * x3);
    }
    g_h[(size_t)n * HID + off] = acc / (den + 1e-16f);
}

// ---------------- BatchNorm ----------------
__global__ void k_bnstats() {
    int col = threadIdx.x;
    int r0 = blockIdx.x * 256;
    int r1 = min(r0 + 256, NN);
    float s = 0.f, s2 = 0.f;
    int r = r0;
    for (; r + 1 < r1; r += 2) {
        float v0 = g_h[(size_t)r * HID + col];
        float v1 = g_h[(size_t)(r + 1) * HID + col];
        s += v0 + v1; s2 += v0 * v0 + v1 * v1;
    }
    for (; r < r1; r++) {
        float v = g_h[(size_t)r * HID + col];
        s += v; s2 += v * v;
    }
    atomicAdd(&g_bnsum[col], s);
    atomicAdd(&g_bnsumsq[col], s2);
}
__global__ void k_bnfinal(const float* __restrict__ gamma, const float* __restrict__ beta) {
    int c = threadIdx.x;
    if (c >= HID) return;
    float mean = g_bnsum[c] * (1.f / NN);
    float var = g_bnsumsq[c] * (1.f / NN) - mean * mean;
    float sc = gamma[c] * rsqrtf(var + EPSBN);
    g_bnA[c] = sc;
    g_bnB[c] = beta[c] - mean * sc;
}

// ---------------- fused layer-2 edge phase: predicated batch-4 + bias + log_softmax ----------------
__global__ void k_l2fused(const float* __restrict__ att,
                          const float* __restrict__ bias2,
                          float* __restrict__ out, int out_size) {
    int n = (blockIdx.x * blockDim.x + threadIdx.x) >> 5;
    int lane = threadIdx.x & 31;
    if (n >= NN) return;
    float xr = g_xr2[n * DOUT + lane];
    float av = att[lane];
    int p = g_off[n], end = g_off[n + 1];
    float den = 0.f, acc = 0.f;
    for (int base = p; base < end; base += 4) {
        int last = end - 1;
        int e1 = min(base + 1, last), e2 = min(base + 2, last), e3 = min(base + 3, last);
        int s0 = g_esrc[base], s1 = g_esrc[e1];
        int s2 = g_esrc[e2],   s3 = g_esrc[e3];
        float m1 = (base + 1 <= last) ? 1.f : 0.f;
        float m2 = (base + 2 <= last) ? 1.f : 0.f;
        float m3 = (base + 3 <= last) ? 1.f : 0.f;
        float x0 = g_xl2[s0 * DOUT + lane];
        float x1 = g_xl2[s1 * DOUT + lane];
        float x2 = g_xl2[s2 * DOUT + lane];
        float x3 = g_xl2[s3 * DOUT + lane];
        float t0 = x0 + xr; t0 = t0 >= 0.f ? t0 : NEGS * t0;
        float t1 = x1 + xr; t1 = t1 >= 0.f ? t1 : NEGS * t1;
        float t2 = x2 + xr; t2 = t2 >= 0.f ? t2 : NEGS * t2;
        float t3 = x3 + xr; t3 = t3 >= 0.f ? t3 : NEGS * t3;
        float f0 = __expf(wsum(t0 * av));
        float f1 = m1 * __expf(wsum(t1 * av));
        float f2 = m2 * __expf(wsum(t2 * av));
        float f3 = m3 * __expf(wsum(t3 * av));
        den += (f0 + f1) + (f2 + f3);
        acc += (f0 * x0 + f1 * x1) + (f2 * x2 + f3 * x3);
    }
    float v = acc / (den + 1e-16f) + bias2[lane];
    out[(size_t)n * DOUT + lane] = v;
    float mx = wmax(v);
    float ex = __expf(v - mx);
    float sum = wsum(ex);
    float ls = v - mx - __logf(sum);
    if (out_size >= 2 * NN * DOUT)
        out[(size_t)NN * DOUT + (size_t)n * DOUT + lane] = ls;
}

// ---------------- launch ----------------
extern "C" void kernel_launch(void* const* d_in, const int* in_sizes, int n_in,
                              void* d_out, int out_size) {
    const float* x     = (const float*)d_in[0];
    const int*   eidx  = (const int*)d_in[1];
    const float* Wl1   = (const float*)d_in[2];
    const float* bl1   = (const float*)d_in[3];
    const float* Wr1   = (const float*)d_in[4];
    const float* br1   = (const float*)d_in[5];
    const float* att1  = (const float*)d_in[6];
    // d_in[7] = bias1: cancels under BatchNorm, unused
    const float* gamma = (const float*)d_in[8];
    const float* beta  = (const float*)d_in[9];
    const float* pa    = (const float*)d_in[10];
    const float* Wl2   = (const float*)d_in[11];
    const float* bl2   = (const float*)d_in[12];
    const float* Wr2   = (const float*)d_in[13];
    const float* br2   = (const float*)d_in[14];
    const float* att2  = (const float*)d_in[15];
    const float* bias2 = (const float*)d_in[16];
    float* out = (float*)d_out;

    const int* src = eidx;
    const int* dst = eidx + EE;

    float *pxl1, *pxr1, *ph, *pxl2, *pxr2;
    cudaGetSymbolAddress((void**)&pxl1, g_xl1);
    cudaGetSymbolAddress((void**)&pxr1, g_xr1);
    cudaGetSymbolAddress((void**)&ph,   g_h);
    cudaGetSymbolAddress((void**)&pxl2, g_xl2);
    cudaGetSymbolAddress((void**)&pxr2, g_xr2);

    // CSR build interleaved with GEMM1 (gemm_tc in the ncu capture slot)
    k_zero<<<(NN + 255) / 256, 256>>>();
    k_deg<<<(EE + 255) / 256, 256>>>(dst);
    k_scan2<<<1, 1024>>>();

    gemm_tc<128, 128, 2, 4, false><<<dim3((NN + 127) / 128, (2 * HID) / 128), 256>>>(
        x, Wl1, bl1, Wr1, br1, nullptr, pxl1, pxr1, NN, DIN, HID);

    k_scatter<<<(EE + 255) / 256, 256>>>(src, dst);
    k_l1fused<<<(NN * HH + 7) / 8, 256>>>(att1);

    k_bnstats<<<(NN + 255) / 256, HID>>>();
    k_bnfinal<<<1, HID>>>(gamma, beta);

    gemm_tc<128, 64, 4, 2, true><<<dim3((NN + 127) / 128, (2 * DOUT) / 64), 256>>>(
        ph, Wl2, bl2, Wr2, br2, pa, pxl2, pxr2, NN, HID, DOUT);
    k_l2fused<<<(NN + 7) / 8, 256>>>(att2, bias2, out, out_size);
}

// round 17
// speedup vs baseline: 1.0549x; 1.0549x over previous
#include <cuda_runtime.h>
#include <math.h>
#include <stdint.h>

#define NN   50000
#define EE   400000
#define DIN  128
#define HH   10
#define HID  320
#define DOUT 32
#define NEGS 0.2f
#define EPSBN 1e-5f

// ---------------- scratch ----------------
__device__ float g_xl1[(size_t)NN * HID];
__device__ float g_xr1[(size_t)NN * HID];
__device__ float g_h  [(size_t)NN * HID];
__device__ float g_xl2[NN * DOUT];
__device__ float g_xr2[NN * DOUT];
__device__ int   g_deg[NN];
__device__ int   g_off[NN + 1];
__device__ int   g_cur[NN];
__device__ int   g_esrc[EE];
__device__ float g_bnsum[HID];
__device__ float g_bnsumsq[HID];
__device__ float g_bnA[HID];
__device__ float g_bnB[HID];

__device__ __forceinline__ float wsum(float v) {
    #pragma unroll
    for (int o = 16; o; o >>= 1) v += __shfl_xor_sync(0xffffffffu, v, o);
    return v;
}
__device__ __forceinline__ float wmax(float v) {
    #pragma unroll
    for (int o = 16; o; o >>= 1) v = fmaxf(v, __shfl_xor_sync(0xffffffffu, v, o));
    return v;
}
__device__ __forceinline__ uint32_t f2tf(float f) {
    uint32_t u;
    asm("cvt.rna.tf32.f32 %0, %1;" : "=r"(u) : "f"(f));
    return u;
}
__device__ __forceinline__ void mma_tf32(float c[4], const uint32_t a[4], const uint32_t b[2]) {
    asm("mma.sync.aligned.m16n8k8.row.col.f32.tf32.tf32.f32 "
        "{%0,%1,%2,%3}, {%4,%5,%6,%7}, {%8,%9}, {%0,%1,%2,%3};"
        : "+f"(c[0]), "+f"(c[1]), "+f"(c[2]), "+f"(c[3])
        : "r"(a[0]), "r"(a[1]), "r"(a[2]), "r"(a[3]), "r"(b[0]), "r"(b[1]));
}

// ---------------- setup ----------------
__global__ void k_zero() {
    int i = blockIdx.x * blockDim.x + threadIdx.x;
    if (i < NN) g_deg[i] = 0;
    if (i < HID) { g_bnsum[i] = 0.f; g_bnsumsq[i] = 0.f; }
}
__global__ void k_deg(const int* __restrict__ dst) {
    int e = blockIdx.x * blockDim.x + threadIdx.x;
    if (e < EE) atomicAdd(&g_deg[dst[e]], 1);
}
__global__ void k_scan2() {
    __shared__ int wsums[32];
    const int t = threadIdx.x;
    const int C = (NN + 1023) / 1024;
    int i0 = t * C;
    int i1 = min(i0 + C, NN);
    if (i0 > NN) i0 = NN;
    int s = 0;
    for (int i = i0; i < i1; i++) s += g_deg[i];
    int lane = t & 31, wid = t >> 5;
    int v = s;
    #pragma unroll
    for (int o = 1; o < 32; o <<= 1) {
        int x = __shfl_up_sync(0xffffffffu, v, o);
        if (lane >= o) v += x;
    }
    if (lane == 31) wsums[wid] = v;
    __syncthreads();
    if (wid == 0) {
        int wv = wsums[lane];
        #pragma unroll
        for (int o = 1; o < 32; o <<= 1) {
            int x = __shfl_up_sync(0xffffffffu, wv, o);
            if (lane >= o) wv += x;
        }
        wsums[lane] = wv;
    }
    __syncthreads();
    int base = v - s + (wid ? wsums[wid - 1] : 0);
    int run = base;
    for (int i = i0; i < i1; i++) {
        g_off[i] = run; g_cur[i] = run;
        run += g_deg[i];
    }
    if (t == 0) g_off[NN] = wsums[31];
}
__global__ void k_scatter(const int* __restrict__ src, const int* __restrict__ dst) {
    int e = blockIdx.x * blockDim.x + threadIdx.x;
    if (e >= EE) return;
    int p = atomicAdd(&g_cur[dst[e]], 1);
    g_esrc[p] = src[e];
}

// ---------------- tf32 tensor-core GEMM, fragment-ordered smem ----------------
template<int BM, int BN, int WROWS, int WCOLS, bool FUSEBN>
__global__ __launch_bounds__(256, 2) void gemm_tc(
        const float* __restrict__ A,
        const float* __restrict__ W1, const float* __restrict__ B1,
        const float* __restrict__ W2, const float* __restrict__ B2,
        const float* __restrict__ pa,
        float* __restrict__ XL, float* __restrict__ XR,
        int M, int K, int NW) {
    constexpr int BK = 32;
    constexpr int WM = BM / WROWS;
    constexpr int WN = BN / WCOLS;
    constexpr int MT = WM / 16;
    constexpr int NT = WN / 8;
    constexpr int MBLK = BM / 16;
    constexpr int NBLK = BN / 8;
    __shared__ __align__(16) uint32_t As_f[BK / 8 * MBLK * 128];
    __shared__ __align__(16) uint32_t Bs_f[BK / 8 * NBLK * 64];
    const int tid = threadIdx.x;
    const int lane = tid & 31;
    const int w = tid >> 5;
    const int wr = w / WCOLS, wc = w % WCOLS;
    const int wm0 = wr * WM, wn0 = wc * WN;
    const int gID = lane >> 2, tIG = lane & 3;
    const int bm = blockIdx.x * BM;
    const int bn = blockIdx.y * BN;
    const float ap = FUSEBN ? pa[0] : 0.f;

    float c[MT][NT][4];
    #pragma unroll
    for (int i = 0; i < MT; i++)
        #pragma unroll
        for (int j = 0; j < NT; j++)
            { c[i][j][0] = 0.f; c[i][j][1] = 0.f; c[i][j][2] = 0.f; c[i][j][3] = 0.f; }

    for (int k0 = 0; k0 < K; k0 += BK) {
        // A tile (fragment-ordered store)
        #pragma unroll
        for (int fid = tid; fid < BM * BK / 4; fid += 256) {
            int r = fid >> 3;
            int kc4 = (fid & 7) * 4;
            float4 v = make_float4(0.f, 0.f, 0.f, 0.f);
            int gr = bm + r;
            if (gr < M) {
                v = *reinterpret_cast<const float4*>(A + (size_t)gr * K + k0 + kc4);
                if (FUSEBN) {
                    float4 sA = *reinterpret_cast<const float4*>(&g_bnA[k0 + kc4]);
                    float4 sB = *reinterpret_cast<const float4*>(&g_bnB[k0 + kc4]);
                    v.x = v.x * sA.x + sB.x; v.x = v.x >= 0.f ? v.x : ap * v.x;
                    v.y = v.y * sA.y + sB.y; v.y = v.y >= 0.f ? v.y : ap * v.y;
                    v.z = v.z * sA.z + sB.z; v.z = v.z >= 0.f ? v.z : ap * v.z;
                    v.w = v.w * sA.w + sB.w; v.w = v.w >= 0.f ? v.w : ap * v.w;
                }
            }
            int mb = r >> 4, m7 = r & 7, mbit = (r >> 3) & 1;
            float vv[4] = {v.x, v.y, v.z, v.w};
            #pragma unroll
            for (int i = 0; i < 4; i++) {
                int k = kc4 + i;
                int kb = k >> 3, k3 = k & 3, kreg = (k >> 2) & 1;
                int o = (m7 * 4 + k3) * 4 + mbit + 2 * kreg;
                As_f[(kb * MBLK + mb) * 128 + (o ^ (kb << 2))] = f2tf(vv[i]);
            }
        }
        // B tile (fragment-ordered store)
        #pragma unroll
        for (int fid = tid; fid < BK * BN / 4; fid += 256) {
            int kr = fid / (BN / 4);
            int nc4 = (fid % (BN / 4)) * 4;
            int gn = bn + nc4;
            const float* Wp; int col;
            if (gn < NW) { Wp = W1; col = gn; } else { Wp = W2; col = gn - NW; }
            float4 v = *reinterpret_cast<const float4*>(Wp + (size_t)(k0 + kr) * NW + col);
            int kb = kr >> 3, k3 = kr & 3, kreg = (kr >> 2) & 1;
            float vv[4] = {v.x, v.y, v.z, v.w};
            #pragma unroll
            for (int i = 0; i < 4; i++) {
                int nn2 = nc4 + i;
                int nb = nn2 >> 3, n7 = nn2 & 7;
                int o = (n7 * 4 + k3) * 2 + kreg;
                Bs_f[(kb * NBLK + nb) * 64 + (o ^ ((nb & 15) << 1))] = f2tf(vv[i]);
            }
        }
        __syncthreads();
        #pragma unroll
        for (int kk = 0; kk < BK / 8; kk++) {
            uint32_t afr[MT][4], bfr[NT][2];
            #pragma unroll
            for (int mt = 0; mt < MT; mt++) {
                int blk = kk * MBLK + (wm0 >> 4) + mt;
                uint4 u = *reinterpret_cast<const uint4*>(
                    &As_f[blk * 128 + ((lane ^ kk) << 2)]);
                afr[mt][0] = u.x; afr[mt][1] = u.y; afr[mt][2] = u.z; afr[mt][3] = u.w;
            }
            #pragma unroll
            for (int nt = 0; nt < NT; nt++) {
                int nb = (wn0 >> 3) + nt;
                int blk = kk * NBLK + nb;
                uint2 u = *reinterpret_cast<const uint2*>(
                    &Bs_f[blk * 64 + ((lane ^ (nb & 15)) << 1)]);
                bfr[nt][0] = u.x; bfr[nt][1] = u.y;
            }
            #pragma unroll
            for (int mt = 0; mt < MT; mt++)
                #pragma unroll
                for (int nt = 0; nt < NT; nt++)
                    mma_tf32(c[mt][nt], afr[mt], bfr[nt]);
        }
        __syncthreads();
    }

    #pragma unroll
    for (int mt = 0; mt < MT; mt++) {
        int r0 = bm + wm0 + mt * 16 + gID;
        int r1 = r0 + 8;
        #pragma unroll
        for (int nt = 0; nt < NT; nt++) {
            int col = bn + wn0 + nt * 8 + tIG * 2;
            float* Xp; const float* Bp; int cc;
            if (col < NW) { Xp = XL; Bp = B1; cc = col; }
            else          { Xp = XR; Bp = B2; cc = col - NW; }
            float b0 = Bp[cc], b1 = Bp[cc + 1];
            if (r0 < M) {
                float2 v = make_float2(c[mt][nt][0] + b0, c[mt][nt][1] + b1);
                *reinterpret_cast<float2*>(Xp + (size_t)r0 * NW + cc) = v;
            }
            if (r1 < M) {
                float2 v = make_float2(c[mt][nt][2] + b0, c[mt][nt][3] + b1);
                *reinterpret_cast<float2*>(Xp + (size_t)r1 * NW + cc) = v;
            }
        }
    }
}

// ---------------- fused layer-1 edge phase: unroll-4 with next-batch index prefetch ----------------
__global__ void k_l1fused(const float* __restrict__ att) {
    int gw = (blockIdx.x * blockDim.x + threadIdx.x) >> 5;
    int lane = threadIdx.x & 31;
    if (gw >= NN * HH) return;
    int n = gw / HH, h = gw - (gw / HH) * HH;
    int off = h * 32 + lane;
    float xr = g_xr1[(size_t)n * HID + off];
    float av = att[off];
    int p = g_off[n], end = g_off[n + 1];
    float den = 0.f, acc = 0.f;
    int i0 = 0, i1 = 0, i2 = 0, i3 = 0;
    if (p + 3 < end) {
        i0 = g_esrc[p]; i1 = g_esrc[p + 1]; i2 = g_esrc[p + 2]; i3 = g_esrc[p + 3];
    }
    for (; p + 3 < end; p += 4) {
        // gathers for current batch issue first (indices already resident)
        float x0 = g_xl1[(size_t)i0 * HID + off];
        float x1 = g_xl1[(size_t)i1 * HID + off];
        float x2 = g_xl1[(size_t)i2 * HID + off];
        float x3 = g_xl1[(size_t)i3 * HID + off];
        // prefetch next batch indices while gathers are in flight
        int np = p + 4;
        int j0 = i0, j1 = i1, j2 = i2, j3 = i3;
        if (np + 3 < end) {
            j0 = g_esrc[np]; j1 = g_esrc[np + 1]; j2 = g_esrc[np + 2]; j3 = g_esrc[np + 3];
        }
        float t0 = x0 + xr; t0 = t0 >= 0.f ? t0 : NEGS * t0;
        float t1 = x1 + xr; t1 = t1 >= 0.f ? t1 : NEGS * t1;
        float t2 = x2 + xr; t2 = t2 >= 0.f ? t2 : NEGS * t2;
        float t3 = x3 + xr; t3 = t3 >= 0.f ? t3 : NEGS * t3;
        float f0 = __expf(wsum(t0 * av));
        float f1 = __expf(wsum(t1 * av));
        float f2 = __expf(wsum(t2 * av));
        float f3 = __expf(wsum(t3 * av));
        den += (f0 + f1) + (f2 + f3);
        acc += (f0 * x0 + f1 * x1) + (f2 * x2 + f3 * x3);
        i0 = j0; i1 = j1; i2 = j2; i3 = j3;
    }
    for (; p < end; p++) {
        int s0 = g_esrc[p];
        float x0 = g_xl1[(size_t)s0 * HID + off];
        float t0 = x0 + xr; t0 = t0 >= 0.f ? t0 : NEGS * t0;
        float f0 = __expf(wsum(t0 * av));
        den += f0; acc += f0 * x0;
    }
    g_h[(size_t)n * HID + off] = acc / (den + 1e-16f);
}

// ---------------- BatchNorm ----------------
__global__ void k_bnstats() {
    int col = threadIdx.x;
    int r0 = blockIdx.x * 256;
    int r1 = min(r0 + 256, NN);
    float s = 0.f, s2 = 0.f;
    for (int r = r0; r < r1; r++) {
        float v = g_h[(size_t)r * HID + col];
        s += v; s2 += v * v;
    }
    atomicAdd(&g_bnsum[col], s);
    atomicAdd(&g_bnsumsq[col], s2);
}
__global__ void k_bnfinal(const float* __restrict__ gamma, const float* __restrict__ beta) {
    int c = threadIdx.x;
    if (c >= HID) return;
    float mean = g_bnsum[c] * (1.f / NN);
    float var = g_bnsumsq[c] * (1.f / NN) - mean * mean;
    float sc = gamma[c] * rsqrtf(var + EPSBN);
    g_bnA[c] = sc;
    g_bnB[c] = beta[c] - mean * sc;
}

// ---------------- fused layer-2 edge phase: prefetch + bias + log_softmax ----------------
__global__ void k_l2fused(const float* __restrict__ att,
                          const float* __restrict__ bias2,
                          float* __restrict__ out, int out_size) {
    int n = (blockIdx.x * blockDim.x + threadIdx.x) >> 5;
    int lane = threadIdx.x & 31;
    if (n >= NN) return;
    float xr = g_xr2[n * DOUT + lane];
    float av = att[lane];
    int p = g_off[n], end = g_off[n + 1];
    float den = 0.f, acc = 0.f;
    int i0 = 0, i1 = 0, i2 = 0, i3 = 0;
    if (p + 3 < end) {
        i0 = g_esrc[p]; i1 = g_esrc[p + 1]; i2 = g_esrc[p + 2]; i3 = g_esrc[p + 3];
    }
    for (; p + 3 < end; p += 4) {
        float x0 = g_xl2[i0 * DOUT + lane];
        float x1 = g_xl2[i1 * DOUT + lane];
        float x2 = g_xl2[i2 * DOUT + lane];
        float x3 = g_xl2[i3 * DOUT + lane];
        int np = p + 4;
        int j0 = i0, j1 = i1, j2 = i2, j3 = i3;
        if (np + 3 < end) {
            j0 = g_esrc[np]; j1 = g_esrc[np + 1]; j2 = g_esrc[np + 2]; j3 = g_esrc[np + 3];
        }
        float t0 = x0 + xr; t0 = t0 >= 0.f ? t0 : NEGS * t0;
        float t1 = x1 + xr; t1 = t1 >= 0.f ? t1 : NEGS * t1;
        float t2 = x2 + xr; t2 = t2 >= 0.f ? t2 : NEGS * t2;
        float t3 = x3 + xr; t3 = t3 >= 0.f ? t3 : NEGS * t3;
        float f0 = __expf(wsum(t0 * av));
        float f1 = __expf(wsum(t1 * av));
        float f2 = __expf(wsum(t2 * av));
        float f3 = __expf(wsum(t3 * av));
        den += (f0 + f1) + (f2 + f3);
        acc += (f0 * x0 + f1 * x1) + (f2 * x2 + f3 * x3);
        i0 = j0; i1 = j1; i2 = j2; i3 = j3;
    }
    for (; p < end; p++) {
        int s0 = g_esrc[p];
        float x0 = g_xl2[s0 * DOUT + lane];
        float t0 = x0 + xr; t0 = t0 >= 0.f ? t0 : NEGS * t0;
        float f0 = __expf(wsum(t0 * av));
        den += f0; acc += f0 * x0;
    }
    float v = acc / (den + 1e-16f) + bias2[lane];
    out[(size_t)n * DOUT + lane] = v;
    float mx = wmax(v);
    float ex = __expf(v - mx);
    float sum = wsum(ex);
    float ls = v - mx - __logf(sum);
    if (out_size >= 2 * NN * DOUT)
        out[(size_t)NN * DOUT + (size_t)n * DOUT + lane] = ls;
}

// ---------------- launch ----------------
extern "C" void kernel_launch(void* const* d_in, const int* in_sizes, int n_in,
                              void* d_out, int out_size) {
    const float* x     = (const float*)d_in[0];
    const int*   eidx  = (const int*)d_in[1];
    const float* Wl1   = (const float*)d_in[2];
    const float* bl1   = (const float*)d_in[3];
    const float* Wr1   = (const float*)d_in[4];
    const float* br1   = (const float*)d_in[5];
    const float* att1  = (const float*)d_in[6];
    // d_in[7] = bias1: cancels under BatchNorm, unused
    const float* gamma = (const float*)d_in[8];
    const float* beta  = (const float*)d_in[9];
    const float* pa    = (const float*)d_in[10];
    const float* Wl2   = (const float*)d_in[11];
    const float* bl2   = (const float*)d_in[12];
    const float* Wr2   = (const float*)d_in[13];
    const float* br2   = (const float*)d_in[14];
    const float* att2  = (const float*)d_in[15];
    const float* bias2 = (const float*)d_in[16];
    float* out = (float*)d_out;

    const int* src = eidx;
    const int* dst = eidx + EE;

    float *pxl1, *pxr1, *ph, *pxl2, *pxr2;
    cudaGetSymbolAddress((void**)&pxl1, g_xl1);
    cudaGetSymbolAddress((void**)&pxr1, g_xr1);
    cudaGetSymbolAddress((void**)&ph,   g_h);
    cudaGetSymbolAddress((void**)&pxl2, g_xl2);
    cudaGetSymbolAddress((void**)&pxr2, g_xr2);

    // CSR build interleaved with GEMM1 (gemm_tc in the ncu capture slot)
    k_zero<<<(NN + 255) / 256, 256>>>();
    k_deg<<<(EE + 255) / 256, 256>>>(dst);
    k_scan2<<<1, 1024>>>();

    gemm_tc<128, 128, 2, 4, false><<<dim3((NN + 127) / 128, (2 * HID) / 128), 256>>>(
        x, Wl1, bl1, Wr1, br1, nullptr, pxl1, pxr1, NN, DIN, HID);

    k_scatter<<<(EE + 255) / 256, 256>>>(src, dst);
    k_l1fused<<<(NN * HH + 7) / 8, 256>>>(att1);

    k_bnstats<<<(NN + 255) / 256, HID>>>();
    k_bnfinal<<<1, HID>>>(gamma, beta);

    gemm_tc<128, 64, 4, 2, true><<<dim3((NN + 127) / 128, (2 * DOUT) / 64), 256>>>(
        ph, Wl2, bl2, Wr2, br2, pa, pxl2, pxr2, NN, HID, DOUT);
    k_l2fused<<<(NN + 7) / 8, 256>>>(att2, bias2, out, out_size);
}